// round 10
// baseline (speedup 1.0000x reference)
#include <cuda_runtime.h>
#include <cstdint>
#include <cstddef>

// Problem constants (fixed-shape problem):
//   grad_last: (B=8, M=4096) float32
//   indices:   (M=4096,) int32, values in [0, N=2048)
//   out:       (8, 4096, 2048) float32  -> 256 MB
//
// out[b, i, j] = (j == indices[i]) ? grad_last[b, i] : 0
//
// Strategy: let the driver's fill path zero the whole buffer
// (cudaMemsetAsync graph node), then a tiny scatter kernel writes the
// 32,768 hot elements (one 4-byte store each; DRAM handles sub-sector
// writes via byte enables, no read-modify-write).

static constexpr unsigned B_DIM = 8;
static constexpr unsigned M_DIM = 4096;
static constexpr unsigned N_DIM = 2048;
static constexpr size_t   OUT_ELEMS = (size_t)B_DIM * M_DIM * N_DIM;

__global__ void __launch_bounds__(256)
scatter_hot(const float* __restrict__ grad_last,
            const int* __restrict__ indices,
            float* __restrict__ out)
{
    // 32768 threads: t = b*4096 + i
    const unsigned t = blockIdx.x * 256u + threadIdx.x;
    const unsigned i = t & (M_DIM - 1u);
    const unsigned b = t >> 12;

    const unsigned ind = (unsigned)__ldg(&indices[i]);
    const float    g   = __ldg(&grad_last[t]);   // grad_last is (B, M) contiguous

    out[(size_t)t * N_DIM + ind] = g;
}

extern "C" void kernel_launch(void* const* d_in, const int* in_sizes, int n_in,
                              void* d_out, int out_size)
{
    const float* grad    = (const float*)d_in[0];
    const int*   indices = (const int*)d_in[1];
    float*       out     = (float*)d_out;

    (void)in_sizes; (void)n_in; (void)out_size;

    // Zero-fill via driver fill path (graph memset node).
    cudaMemsetAsync(out, 0, OUT_ELEMS * sizeof(float));

    // Scatter the 32768 non-zero elements (serialized after the fill).
    scatter_hot<<<(B_DIM * M_DIM) / 256, 256>>>(grad, indices, out);
}

// round 11
// speedup vs baseline: 1.1463x; 1.1463x over previous
#include <cuda_runtime.h>
#include <cstdint>
#include <cstddef>

// Problem constants (fixed-shape problem):
//   grad_last: (B=8, M=4096) float32
//   indices:   (M=4096,) int32, values in [0, N=2048)
//   out:       (8, 4096, 2048) float32  -> 256 MB
//
// out[b, i, j] = (j == indices[i]) ? grad_last[b, i] : 0
//
// ROOFLINE KERNEL (verified across 5 alternative fill mechanisms, all equal
// or worse): HBM write-bound at ~6.6 TB/s effective; floor ~40 us for 256 MB.
//
// One block (128 threads) per output row (2048 floats = 512 float4).
// Each thread writes 4 float4 (64 B), batched back-to-back for write MLP.
// Store j of the block covers a contiguous 2 KB slab -> perfectly coalesced,
// full 32B sectors. Streaming store hint (.cs): output has zero reuse.

static constexpr unsigned B_DIM = 8;
static constexpr unsigned M_DIM = 4096;
static constexpr unsigned ROWS  = B_DIM * M_DIM;            // 32768 blocks
static constexpr unsigned VEC_PER_ROW = 512;                // 2048 / 4

__global__ void __launch_bounds__(128)
reduce_max_grad_scatter(const float* __restrict__ grad_last,
                        const int* __restrict__ indices,
                        float4* __restrict__ out)
{
    const unsigned row = blockIdx.x;          // b*4096 + i
    const unsigned i   = row & (M_DIM - 1u);
    const unsigned b   = row >> 12;
    const unsigned tid = threadIdx.x;

    // Both loads are block-uniform -> L1 broadcast hits.
    const unsigned ind = (unsigned)__ldg(&indices[i]);
    const float    g   = __ldg(&grad_last[b * M_DIM + i]);

    const unsigned target = ind >> 2;         // which float4 holds the hot lane
    const unsigned lane   = ind & 3u;

    float4* o = out + (size_t)row * VEC_PER_ROW + tid;

#pragma unroll
    for (int j = 0; j < 4; j++) {
        const unsigned q = j * 128u + tid;
        float4 v = make_float4(0.f, 0.f, 0.f, 0.f);
        if (q == target) {                    // taken by exactly 1 of 512 (thread,j)
            v.x = (lane == 0u) ? g : 0.f;
            v.y = (lane == 1u) ? g : 0.f;
            v.z = (lane == 2u) ? g : 0.f;
            v.w = (lane == 3u) ? g : 0.f;
        }
        __stcs(&o[j * 128], v);               // streaming store, evict-first
    }
}

extern "C" void kernel_launch(void* const* d_in, const int* in_sizes, int n_in,
                              void* d_out, int out_size)
{
    const float* grad    = (const float*)d_in[0];
    const int*   indices = (const int*)d_in[1];
    float4*      out     = (float4*)d_out;

    (void)in_sizes; (void)n_in; (void)out_size;

    reduce_max_grad_scatter<<<ROWS, 128>>>(grad, indices, out);
}